// round 8
// baseline (speedup 1.0000x reference)
#include <cuda_runtime.h>

#define NN 4096
#define EE 16384
#define DD 13
#define RR 128
#define NP 4
#define HOSTRIDE 132
#define PBLK 8
#define EPB  (EE / PBLK)
#define GCAP 2304

__device__ int   g_groups[PBLK * GCAP];
__device__ int   g_cnt4[PBLK];
__device__ float g_nodes16[NN * 16];

// k_main smem layout (floats)
#define S_BP   0
#define S_BPB  (NP * DD * RR)
#define S_HO   (S_BPB + NP * RR)
#define S_HOB  (S_HO + 3 * NP * DD * HOSTRIDE)
#define S_WTOT (S_HOB + 3 * NP * DD)          // 27916 floats (16B aligned)
#define SCR_PW (3 * 4 * 128)                  // 1536 floats per warp scratch
#define S_TOT  (S_WTOT + 16 * SCR_PW)         // 52492 floats = 209968 B

// ---- prep: bucket sort by type key into padded groups of 4; fill nodes16 ----
__global__ void __launch_bounds__(1024, 1) k_prep(const int* __restrict__ et,
                                                  const float* __restrict__ nodes,
                                                  float* __restrict__ out) {
    __shared__ int hist[64], bstart[64], cursor[64], gb[64];
    __shared__ short sorted[EPB];
    __shared__ unsigned char keys[EPB], skey[EPB];
    const int tid = threadIdx.x;
    const int bi  = blockIdx.x;
    const int base = bi * EPB;

    for (int i = tid; i < NN * DD / PBLK; i += 1024) out[bi * (NN * DD / PBLK) + i] = 0.f;
    // padded node buffer rows [bi*512, bi*512+512)
    for (int i = tid; i < (NN / PBLK) * 16; i += 1024) {
        int row = i >> 4, c = i & 15;
        int gr = bi * (NN / PBLK) + row;
        g_nodes16[gr * 16 + c] = (c < DD) ? nodes[gr * DD + c] : 0.f;
    }
    for (int i = tid; i < GCAP; i += 1024) g_groups[bi * GCAP + i] = -1;

    if (tid < 64) hist[tid] = 0;
    __syncthreads();
    for (int i = tid; i < EPB; i += 1024) {
        int e = base + i;
        int k = __ldg(et + e * 3) * 16 + __ldg(et + e * 3 + 1) * 4 + __ldg(et + e * 3 + 2);
        keys[i] = (unsigned char)k;
        atomicAdd(&hist[k], 1);
    }
    __syncthreads();
    if (tid == 0) {
        int run = 0, rg = 0;
        for (int k = 0; k < 64; k++) {
            bstart[k] = run; cursor[k] = run; run += hist[k];
            gb[k] = rg; rg += (hist[k] + 3) >> 2;
        }
        g_cnt4[bi] = rg;
    }
    __syncthreads();
    for (int i = tid; i < EPB; i += 1024) {
        int k = keys[i];
        int pos = atomicAdd(&cursor[k], 1);
        sorted[pos] = (short)i;
        skey[pos] = (unsigned char)k;
    }
    __syncthreads();
    for (int i = tid; i < EPB; i += 1024) {
        int k = skey[i];
        int r = i - bstart[k];
        g_groups[bi * GCAP + gb[k] * 4 + r] = base + (int)sorted[i];
    }
}

// ---- batched reduction: 13 streams over each 8-lane group (4 edges at once)
// Final: lane l (=lane&7) holds streams sid0(l) [+ sid0+1 if nst(l)==2]:
// sid0: l=0:0 1:2 2:4 3:6 4:7 5:9 6:10 7:12 ; nst: 2,2,2,1,2,1,2,1
__device__ __forceinline__ void reduce13_8(float* v, int l) {
    {
        float o[13];
#pragma unroll
        for (int i = 0; i < 13; i++) o[i] = __shfl_xor_sync(0xffffffffu, v[i], 4);
        if (l & 4) {
#pragma unroll
            for (int i = 0; i < 6; i++) v[i] = v[i + 7] + o[i + 7];
        } else {
#pragma unroll
            for (int i = 0; i < 7; i++) v[i] = v[i] + o[i];
        }
    }
    {
        float o[7];
#pragma unroll
        for (int i = 0; i < 7; i++) o[i] = __shfl_xor_sync(0xffffffffu, v[i], 2);
        if (!(l & 4)) {
            if (l & 2) { v[0] = v[4] + o[4]; v[1] = v[5] + o[5]; v[2] = v[6] + o[6]; }
            else { v[0] = v[0] + o[0]; v[1] = v[1] + o[1]; v[2] = v[2] + o[2]; v[3] = v[3] + o[3]; }
        } else {
            if (l & 2) { v[0] = v[3] + o[3]; v[1] = v[4] + o[4]; v[2] = v[5] + o[5]; }
            else { v[0] = v[0] + o[0]; v[1] = v[1] + o[1]; v[2] = v[2] + o[2]; }
        }
    }
    {
        float o[4];
#pragma unroll
        for (int i = 0; i < 4; i++) o[i] = __shfl_xor_sync(0xffffffffu, v[i], 1);
        if (!(l & 4) && !(l & 2)) {           // 4 streams
            if (l & 1) { v[0] = v[2] + o[2]; v[1] = v[3] + o[3]; }
            else { v[0] = v[0] + o[0]; v[1] = v[1] + o[1]; }
        } else {                              // 3 streams
            if (l & 1) { v[0] = v[2] + o[2]; }
            else { v[0] = v[0] + o[0]; v[1] = v[1] + o[1]; }
        }
    }
}

__global__ void __launch_bounds__(512, 1) k_main(
    const float* __restrict__ bp_params,
    const float* __restrict__ bp_bias,
    const float* __restrict__ ho_params,   // [3][NP][128][13]
    const float* __restrict__ ho_bias,
    const int*   __restrict__ edges,
    const int*   __restrict__ et,
    float*       __restrict__ out)
{
    extern __shared__ float sm[];
    for (int i = threadIdx.x; i < NP * DD * RR; i += blockDim.x) sm[S_BP + i] = bp_params[i];
    for (int i = threadIdx.x; i < NP * RR; i += blockDim.x)      sm[S_BPB + i] = bp_bias[i];
#pragma unroll 4
    for (int i = threadIdx.x; i < 3 * NP * RR * DD; i += blockDim.x) {
        int d  = i % DD;
        int rd = i / DD;
        int r  = rd & (RR - 1);
        int sp = rd >> 7;
        sm[S_HO + (sp * DD + d) * HOSTRIDE + r] = ho_params[i];
    }
    for (int i = threadIdx.x; i < 3 * NP * DD; i += blockDim.x)  sm[S_HOB + i] = ho_bias[i];
    __syncthreads();

    const int lane = threadIdx.x & 31;
    const int warp = threadIdx.x >> 5;
    const int wid  = blockIdx.x * (blockDim.x >> 5) + warp;
    const int nw   = gridDim.x * (blockDim.x >> 5);
    float* scr = sm + S_WTOT + warp * SCR_PW;

    const int g  = lane >> 3;          // edge within group (H=8 phase)
    const int l  = lane & 7;           // sub-lane
    const int sid0 = ((lane & 4) ? 7 : 0) + ((lane & 2) ? ((lane & 4) ? 3 : 4) : 0) + (lane & 1) * 2;
    const int nst  = (lane & 1) ? (((lane & 7) == 1) ? 2 : 1) : 2;

    int pre[PBLK + 1];
    pre[0] = 0;
#pragma unroll
    for (int b = 0; b < PBLK; b++) pre[b + 1] = pre[b] + __ldg(&g_cnt4[b]);
    const int total = pre[PBLK];

#pragma unroll 1
    for (int u = wid; u < total; u += nw) {
        int bi = 0;
#pragma unroll
        for (int b = 1; b < PBLK; b++) bi += (u >= pre[b]);
        const int local = u - pre[bi];
        const int* gp = g_groups + bi * GCAP + local * 4;
        int ids[4];
#pragma unroll
        for (int b = 0; b < 4; b++) ids[b] = gp[b];
        int vmask = 1;
#pragma unroll
        for (int b = 1; b < 4; b++) {
            if (ids[b] >= 0) vmask |= (1 << b);
            else ids[b] = ids[0];
        }
        const int ty0 = __ldg(et + ids[0] * 3 + 0);
        const int ty1 = __ldg(et + ids[0] * 3 + 1);
        const int ty2 = __ldg(et + ids[0] * 3 + 2);
        const int ty[3] = {ty0, ty1, ty2};

        int nd[4][3];
#pragma unroll
        for (int b = 0; b < 4; b++)
#pragma unroll
            for (int s = 0; s < 3; s++)
                nd[b][s] = __ldg(edges + ids[b] * 3 + s);

        // ======== stage 1 (H=32: lane owns r=4*lane..+3; edges serialized) ====
#pragma unroll
        for (int s = 0; s < 3; s++) {
            const float* wb = sm + S_BP + ty[s] * DD * RR;
            float4 bias = reinterpret_cast<const float4*>(sm + S_BPB + ty[s] * RR)[lane];
            float4 acc0 = bias, acc1 = bias, acc2 = bias, acc3 = bias;
#pragma unroll
            for (int j = 0; j < 4; j++) {
                float4 rv0 = __ldg(reinterpret_cast<const float4*>(g_nodes16 + nd[0][s] * 16) + j);
                float4 rv1 = __ldg(reinterpret_cast<const float4*>(g_nodes16 + nd[1][s] * 16) + j);
                float4 rv2 = __ldg(reinterpret_cast<const float4*>(g_nodes16 + nd[2][s] * 16) + j);
                float4 rv3 = __ldg(reinterpret_cast<const float4*>(g_nodes16 + nd[3][s] * 16) + j);
                const int dmax = (j == 3) ? 1 : 4;
#pragma unroll
                for (int dc = 0; dc < dmax; dc++) {
                    const int d = j * 4 + dc;
                    float4 w = reinterpret_cast<const float4*>(wb + d * RR)[lane];
                    float r0 = (dc == 0) ? rv0.x : (dc == 1) ? rv0.y : (dc == 2) ? rv0.z : rv0.w;
                    float r1 = (dc == 0) ? rv1.x : (dc == 1) ? rv1.y : (dc == 2) ? rv1.z : rv1.w;
                    float r2 = (dc == 0) ? rv2.x : (dc == 1) ? rv2.y : (dc == 2) ? rv2.z : rv2.w;
                    float r3 = (dc == 0) ? rv3.x : (dc == 1) ? rv3.y : (dc == 2) ? rv3.z : rv3.w;
                    acc0.x = fmaf(r0, w.x, acc0.x); acc0.y = fmaf(r0, w.y, acc0.y);
                    acc0.z = fmaf(r0, w.z, acc0.z); acc0.w = fmaf(r0, w.w, acc0.w);
                    acc1.x = fmaf(r1, w.x, acc1.x); acc1.y = fmaf(r1, w.y, acc1.y);
                    acc1.z = fmaf(r1, w.z, acc1.z); acc1.w = fmaf(r1, w.w, acc1.w);
                    acc2.x = fmaf(r2, w.x, acc2.x); acc2.y = fmaf(r2, w.y, acc2.y);
                    acc2.z = fmaf(r2, w.z, acc2.z); acc2.w = fmaf(r2, w.w, acc2.w);
                    acc3.x = fmaf(r3, w.x, acc3.x); acc3.y = fmaf(r3, w.y, acc3.y);
                    acc3.z = fmaf(r3, w.z, acc3.z); acc3.w = fmaf(r3, w.w, acc3.w);
                }
            }
            // relu + stash to per-warp scratch  [s][b][r]
            float4* dst = reinterpret_cast<float4*>(scr + s * 4 * 128);
            acc0.x = fmaxf(acc0.x, 0.f); acc0.y = fmaxf(acc0.y, 0.f);
            acc0.z = fmaxf(acc0.z, 0.f); acc0.w = fmaxf(acc0.w, 0.f);
            dst[0 * 32 + lane] = acc0;
            acc1.x = fmaxf(acc1.x, 0.f); acc1.y = fmaxf(acc1.y, 0.f);
            acc1.z = fmaxf(acc1.z, 0.f); acc1.w = fmaxf(acc1.w, 0.f);
            dst[1 * 32 + lane] = acc1;
            acc2.x = fmaxf(acc2.x, 0.f); acc2.y = fmaxf(acc2.y, 0.f);
            acc2.z = fmaxf(acc2.z, 0.f); acc2.w = fmaxf(acc2.w, 0.f);
            dst[2 * 32 + lane] = acc2;
            acc3.x = fmaxf(acc3.x, 0.f); acc3.y = fmaxf(acc3.y, 0.f);
            acc3.z = fmaxf(acc3.z, 0.f); acc3.w = fmaxf(acc3.w, 0.f);
            dst[3 * 32 + lane] = acc3;
        }
        __syncwarp();

        // ======== stage 2 (H=8: lane (g,l) owns edge g, r=16l..16l+15) =======
        float4 t8[3][4];
#pragma unroll
        for (int s = 0; s < 3; s++)
#pragma unroll
            for (int k = 0; k < 4; k++)
                t8[s][k] = reinterpret_cast<const float4*>(scr + (s * 4 + g) * 128)[l * 4 + k];
        __syncwarp();   // scratch free for next iteration's stores

        const int myedge = ids[(g == 0) ? 0 : ((g == 1) ? 1 : ((g == 2) ? 2 : 3))];
        (void)myedge;
        const bool val = (vmask >> g) & 1;
        int ndg[3];
#pragma unroll
        for (int s = 0; s < 3; s++)
            ndg[s] = (g == 0) ? nd[0][s] : ((g == 1) ? nd[1][s] : ((g == 2) ? nd[2][s] : nd[3][s]));

#pragma unroll
        for (int s = 0; s < 3; s++) {
            const int jj = (s == 0) ? 1 : 0;
            const int kk = (s == 2) ? 1 : 2;
            float4 f[4];
#pragma unroll
            for (int k = 0; k < 4; k++) {
                f[k].x = t8[jj][k].x * t8[kk][k].x;
                f[k].y = t8[jj][k].y * t8[kk][k].y;
                f[k].z = t8[jj][k].z * t8[kk][k].z;
                f[k].w = t8[jj][k].w * t8[kk][k].w;
            }
            const float* wh = sm + S_HO + (s * NP + ty[s]) * DD * HOSTRIDE;
            float ms[13];
#pragma unroll
            for (int d = 0; d < 13; d++) {
                float acc = 0.f;
#pragma unroll
                for (int k = 0; k < 4; k++) {
                    float4 w = *reinterpret_cast<const float4*>(wh + d * HOSTRIDE + (l * 4 + k) * 4);
                    acc = fmaf(f[k].w, w.w, fmaf(f[k].z, w.z, fmaf(f[k].y, w.y, fmaf(f[k].x, w.x, acc))));
                }
                ms[d] = acc;
            }
            reduce13_8(ms, l);
            if (val) {
                const float* hb = sm + S_HOB + (s * NP + ty[s]) * DD;
                float* dst = out + ndg[s] * DD;
                atomicAdd(dst + sid0, ms[0] + hb[sid0]);
                if (nst == 2)
                    atomicAdd(dst + sid0 + 1, ms[1] + hb[sid0 + 1]);
            }
        }
    }
}

extern "C" void kernel_launch(void* const* d_in, const int* in_sizes, int n_in,
                              void* d_out, int out_size) {
    const float* nodes      = (const float*)d_in[0];
    const float* bp_params  = (const float*)d_in[1];
    const float* bp_bias    = (const float*)d_in[2];
    const float* ho_params  = (const float*)d_in[3];
    const float* ho_bias    = (const float*)d_in[4];
    const int*   edges      = (const int*)d_in[5];
    const int*   edge_types = (const int*)d_in[6];
    float* out = (float*)d_out;

    int sms = 0;
    cudaDeviceGetAttribute(&sms, cudaDevAttrMultiProcessorCount, 0);
    if (sms <= 0) sms = 148;
    cudaFuncSetAttribute(k_main, cudaFuncAttributeMaxDynamicSharedMemorySize, S_TOT * 4);

    k_prep<<<PBLK, 1024>>>(edge_types, nodes, out);
    k_main<<<sms, 512, S_TOT * 4>>>(bp_params, bp_bias, ho_params, ho_bias,
                                    edges, edge_types, out);
}

// round 9
// speedup vs baseline: 1.9266x; 1.9266x over previous
#include <cuda_runtime.h>

#define NN 4096
#define EE 16384
#define DD 13
#define RR 128
#define NP 4
#define HOSTRIDE 132
#define PBLK 8
#define EPB  (EE / PBLK)
#define GCAP 2304

typedef unsigned long long u64;

__device__ int   g_groups[PBLK * GCAP];
__device__ int   g_cnt4[PBLK];
__device__ float g_nodes16[NN * 16];

// k_main smem layout (floats)
#define S_BP   0
#define S_BPB  (NP * DD * RR)
#define S_HO   (S_BPB + NP * RR)
#define S_HOB  (S_HO + 3 * NP * DD * HOSTRIDE)
#define S_TOT  (S_HOB + 3 * NP * DD)   // ~109.1 KiB

// ---------------- f32x2 packed helpers (Blackwell FFMA2 path) ----------------
__device__ __forceinline__ u64 pk2(float lo, float hi) {
    u64 r; asm("mov.b64 %0,{%1,%2};" : "=l"(r) : "f"(lo), "f"(hi)); return r;
}
__device__ __forceinline__ u64 dup2(float v) {
    u64 r; asm("mov.b64 %0,{%1,%1};" : "=l"(r) : "f"(v)); return r;
}
__device__ __forceinline__ void up2(float& lo, float& hi, u64 v) {
    asm("mov.b64 {%0,%1},%2;" : "=f"(lo), "=f"(hi) : "l"(v));
}
__device__ __forceinline__ u64 fma2(u64 a, u64 b, u64 c) {
    u64 d; asm("fma.rn.f32x2 %0,%1,%2,%3;" : "=l"(d) : "l"(a), "l"(b), "l"(c)); return d;
}
__device__ __forceinline__ u64 mul2(u64 a, u64 b) {
    u64 d; asm("mul.rn.f32x2 %0,%1,%2;" : "=l"(d) : "l"(a), "l"(b)); return d;
}
__device__ __forceinline__ u64 add2(u64 a, u64 b) {
    u64 d; asm("add.rn.f32x2 %0,%1,%2;" : "=l"(d) : "l"(a), "l"(b)); return d;
}
__device__ __forceinline__ u64 relu2(u64 v) {
    float lo, hi; up2(lo, hi, v);
    return pk2(fmaxf(lo, 0.f), fmaxf(hi, 0.f));
}

// ---- prep: bucket sort by type key into padded groups of 4; fill nodes16 ----
__global__ void __launch_bounds__(1024, 1) k_prep(const int* __restrict__ et,
                                                  const float* __restrict__ nodes,
                                                  float* __restrict__ out) {
    __shared__ int hist[64], bstart[64], cursor[64], gb[64];
    __shared__ short sorted[EPB];
    __shared__ unsigned char keys[EPB], skey[EPB];
    const int tid = threadIdx.x;
    const int bi  = blockIdx.x;
    const int base = bi * EPB;

    for (int i = tid; i < NN * DD / PBLK; i += 1024) out[bi * (NN * DD / PBLK) + i] = 0.f;
    for (int i = tid; i < (NN / PBLK) * 16; i += 1024) {
        int row = i >> 4, c = i & 15;
        int gr = bi * (NN / PBLK) + row;
        g_nodes16[gr * 16 + c] = (c < DD) ? nodes[gr * DD + c] : 0.f;
    }
    for (int i = tid; i < GCAP; i += 1024) g_groups[bi * GCAP + i] = -1;

    if (tid < 64) hist[tid] = 0;
    __syncthreads();
    for (int i = tid; i < EPB; i += 1024) {
        int e = base + i;
        int k = __ldg(et + e * 3) * 16 + __ldg(et + e * 3 + 1) * 4 + __ldg(et + e * 3 + 2);
        keys[i] = (unsigned char)k;
        atomicAdd(&hist[k], 1);
    }
    __syncthreads();
    if (tid == 0) {
        int run = 0, rg = 0;
        for (int k = 0; k < 64; k++) {
            bstart[k] = run; cursor[k] = run; run += hist[k];
            gb[k] = rg; rg += (hist[k] + 3) >> 2;
        }
        g_cnt4[bi] = rg;
    }
    __syncthreads();
    for (int i = tid; i < EPB; i += 1024) {
        int k = keys[i];
        int pos = atomicAdd(&cursor[k], 1);
        sorted[pos] = (short)i;
        skey[pos] = (unsigned char)k;
    }
    __syncthreads();
    for (int i = tid; i < EPB; i += 1024) {
        int k = skey[i];
        int r = i - bstart[k];
        g_groups[bi * GCAP + gb[k] * 4 + r] = base + (int)sorted[i];
    }
}

// ---- packed warp reduction of 13 f32x2 streams (both edges of a pair) -------
__device__ __forceinline__ u64 tree13p(u64* v, int lane) {
    {
        u64 o[13];
#pragma unroll
        for (int i = 0; i < 13; i++) o[i] = __shfl_xor_sync(0xffffffffu, v[i], 16);
        if (lane & 16) {
#pragma unroll
            for (int i = 0; i < 6; i++) v[i] = add2(v[i + 7], o[i + 7]);
        } else {
#pragma unroll
            for (int i = 0; i < 7; i++) v[i] = add2(v[i], o[i]);
        }
    }
    {
        u64 o[7];
#pragma unroll
        for (int i = 0; i < 7; i++) o[i] = __shfl_xor_sync(0xffffffffu, v[i], 8);
        if (!(lane & 16)) {
            if (lane & 8) { v[0] = add2(v[4], o[4]); v[1] = add2(v[5], o[5]); v[2] = add2(v[6], o[6]); }
            else { v[0] = add2(v[0], o[0]); v[1] = add2(v[1], o[1]); v[2] = add2(v[2], o[2]); v[3] = add2(v[3], o[3]); }
        } else {
            if (lane & 8) { v[0] = add2(v[3], o[3]); v[1] = add2(v[4], o[4]); v[2] = add2(v[5], o[5]); }
            else { v[0] = add2(v[0], o[0]); v[1] = add2(v[1], o[1]); v[2] = add2(v[2], o[2]); }
        }
    }
    {
        u64 o[4];
#pragma unroll
        for (int i = 0; i < 4; i++) o[i] = __shfl_xor_sync(0xffffffffu, v[i], 4);
        bool four = ((lane & 24) == 0);
        if (lane & 4) {
            v[0] = add2(v[2], o[2]);
            if (four) v[1] = add2(v[3], o[3]);
        } else {
            v[0] = add2(v[0], o[0]);
            v[1] = add2(v[1], o[1]);
        }
    }
    {
        u64 o0 = __shfl_xor_sync(0xffffffffu, v[0], 2);
        u64 o1 = __shfl_xor_sync(0xffffffffu, v[1], 2);
        v[0] = (lane & 2) ? add2(v[1], o1) : add2(v[0], o0);
    }
    {
        u64 o0 = __shfl_xor_sync(0xffffffffu, v[0], 1);
        v[0] = add2(v[0], o0);
    }
    return v[0];
}

__global__ void __launch_bounds__(512, 1) k_main(
    const float* __restrict__ bp_params,
    const float* __restrict__ bp_bias,
    const float* __restrict__ ho_params,   // [3][NP][128][13]
    const float* __restrict__ ho_bias,
    const int*   __restrict__ edges,
    const int*   __restrict__ et,
    float*       __restrict__ out)
{
    extern __shared__ float sm[];
    for (int i = threadIdx.x; i < NP * DD * RR; i += blockDim.x) sm[S_BP + i] = bp_params[i];
    for (int i = threadIdx.x; i < NP * RR; i += blockDim.x)      sm[S_BPB + i] = bp_bias[i];
#pragma unroll 4
    for (int i = threadIdx.x; i < 3 * NP * RR * DD; i += blockDim.x) {
        int d  = i % DD;
        int rd = i / DD;
        int r  = rd & (RR - 1);
        int sp = rd >> 7;
        sm[S_HO + (sp * DD + d) * HOSTRIDE + r] = ho_params[i];
    }
    for (int i = threadIdx.x; i < 3 * NP * DD; i += blockDim.x)  sm[S_HOB + i] = ho_bias[i];
    __syncthreads();

    const int lane = threadIdx.x & 31;
    const int wid  = blockIdx.x * (blockDim.x >> 5) + (threadIdx.x >> 5);
    const int nw   = gridDim.x * (blockDim.x >> 5);

    int pre[PBLK + 1];
    pre[0] = 0;
#pragma unroll
    for (int b = 0; b < PBLK; b++) pre[b + 1] = pre[b] + __ldg(&g_cnt4[b]);
    const int total = pre[PBLK];

    const int b4 = (lane >> 4) & 1, b3 = (lane >> 3) & 1, b2 = (lane >> 2) & 1,
              b1 = (lane >> 1) & 1, b0 = lane & 1;
    const bool alive = (b0 == 0) && !(b1 && b2 && (b4 | b3));
    const int sid = 7 * b4 + (b4 ? 3 * b3 : 4 * b3) + 2 * b2 + b1;

#pragma unroll 1
    for (int u = wid; u < total; u += nw) {
        int bi = 0;
#pragma unroll
        for (int b = 1; b < PBLK; b++) bi += (u >= pre[b]);
        const int local = u - pre[bi];
        const int* gp = g_groups + bi * GCAP + local * 4;
        int ids[4];
#pragma unroll
        for (int b = 0; b < 4; b++) ids[b] = gp[b];
        int vmask = 1;
#pragma unroll
        for (int b = 1; b < 4; b++) {
            if (ids[b] >= 0) vmask |= (1 << b);
            else ids[b] = ids[0];
        }
        const int ty0 = __ldg(et + ids[0] * 3 + 0);
        const int ty1 = __ldg(et + ids[0] * 3 + 1);
        const int ty2 = __ldg(et + ids[0] * 3 + 2);
        const int ty[3] = {ty0, ty1, ty2};

        int nd[4][3];
#pragma unroll
        for (int b = 0; b < 4; b++)
#pragma unroll
            for (int s = 0; s < 3; s++)
                nd[b][s] = __ldg(edges + ids[b] * 3 + s);

        // ===== stage 1: packed accs over edge pairs (0,1) and (2,3) ==========
        u64 t01[3][4], t23[3][4];
#pragma unroll
        for (int s = 0; s < 3; s++) {
            const float* wb = sm + S_BP + ty[s] * DD * RR;
            float4 bias = reinterpret_cast<const float4*>(sm + S_BPB + ty[s] * RR)[lane];
            u64 a01[4], a23[4];
            a01[0] = dup2(bias.x); a01[1] = dup2(bias.y);
            a01[2] = dup2(bias.z); a01[3] = dup2(bias.w);
            a23[0] = a01[0]; a23[1] = a01[1]; a23[2] = a01[2]; a23[3] = a01[3];
#pragma unroll
            for (int j = 0; j < 4; j++) {
                float4 rv0 = __ldg(reinterpret_cast<const float4*>(g_nodes16 + nd[0][s] * 16) + j);
                float4 rv1 = __ldg(reinterpret_cast<const float4*>(g_nodes16 + nd[1][s] * 16) + j);
                float4 rv2 = __ldg(reinterpret_cast<const float4*>(g_nodes16 + nd[2][s] * 16) + j);
                float4 rv3 = __ldg(reinterpret_cast<const float4*>(g_nodes16 + nd[3][s] * 16) + j);
                const int dmax = (j == 3) ? 1 : 4;
#pragma unroll
                for (int dc = 0; dc < dmax; dc++) {
                    const int d = j * 4 + dc;
                    float4 w = reinterpret_cast<const float4*>(wb + d * RR)[lane];
                    float r0 = (dc == 0) ? rv0.x : (dc == 1) ? rv0.y : (dc == 2) ? rv0.z : rv0.w;
                    float r1 = (dc == 0) ? rv1.x : (dc == 1) ? rv1.y : (dc == 2) ? rv1.z : rv1.w;
                    float r2 = (dc == 0) ? rv2.x : (dc == 1) ? rv2.y : (dc == 2) ? rv2.z : rv2.w;
                    float r3 = (dc == 0) ? rv3.x : (dc == 1) ? rv3.y : (dc == 2) ? rv3.z : rv3.w;
                    u64 rr01 = pk2(r0, r1), rr23 = pk2(r2, r3);
                    u64 wx = dup2(w.x), wy = dup2(w.y), wz = dup2(w.z), ww = dup2(w.w);
                    a01[0] = fma2(rr01, wx, a01[0]);
                    a01[1] = fma2(rr01, wy, a01[1]);
                    a01[2] = fma2(rr01, wz, a01[2]);
                    a01[3] = fma2(rr01, ww, a01[3]);
                    a23[0] = fma2(rr23, wx, a23[0]);
                    a23[1] = fma2(rr23, wy, a23[1]);
                    a23[2] = fma2(rr23, wz, a23[2]);
                    a23[3] = fma2(rr23, ww, a23[3]);
                }
            }
#pragma unroll
            for (int c = 0; c < 4; c++) {
                t01[s][c] = relu2(a01[c]);
                t23[s][c] = relu2(a23[c]);
            }
        }

        // ===== stage 2: packed products + packed FMA + packed trees ==========
#pragma unroll
        for (int s = 0; s < 3; s++) {
            const int jj = (s == 0) ? 1 : 0;
            const int kk = (s == 2) ? 1 : 2;
            u64 f01[4], f23[4];
#pragma unroll
            for (int c = 0; c < 4; c++) {
                f01[c] = mul2(t01[jj][c], t01[kk][c]);
                f23[c] = mul2(t23[jj][c], t23[kk][c]);
            }
            const float* wh = sm + S_HO + (s * NP + ty[s]) * DD * HOSTRIDE;
            const float* hb = sm + S_HOB + (s * NP + ty[s]) * DD;
            u64 ms01[DD], ms23[DD];
#pragma unroll
            for (int d = 0; d < DD; d++) {
                float4 w = reinterpret_cast<const float4*>(wh + d * HOSTRIDE)[lane];
                u64 wx = dup2(w.x), wy = dup2(w.y), wz = dup2(w.z), ww = dup2(w.w);
                u64 m0 = mul2(f01[0], wx);
                m0 = fma2(f01[1], wy, m0);
                m0 = fma2(f01[2], wz, m0);
                ms01[d] = fma2(f01[3], ww, m0);
                u64 m1 = mul2(f23[0], wx);
                m1 = fma2(f23[1], wy, m1);
                m1 = fma2(f23[2], wz, m1);
                ms23[d] = fma2(f23[3], ww, m1);
            }
            u64 r01 = tree13p(ms01, lane);
            u64 r23 = tree13p(ms23, lane);
            if (alive) {
                float bias = hb[sid];
                float lo, hi;
                up2(lo, hi, r01);
                atomicAdd(out + nd[0][s] * DD + sid, lo + bias);
                if (vmask & 2) atomicAdd(out + nd[1][s] * DD + sid, hi + bias);
                up2(lo, hi, r23);
                if (vmask & 4) atomicAdd(out + nd[2][s] * DD + sid, lo + bias);
                if (vmask & 8) atomicAdd(out + nd[3][s] * DD + sid, hi + bias);
            }
        }
    }
}

extern "C" void kernel_launch(void* const* d_in, const int* in_sizes, int n_in,
                              void* d_out, int out_size) {
    const float* nodes      = (const float*)d_in[0];
    const float* bp_params  = (const float*)d_in[1];
    const float* bp_bias    = (const float*)d_in[2];
    const float* ho_params  = (const float*)d_in[3];
    const float* ho_bias    = (const float*)d_in[4];
    const int*   edges      = (const int*)d_in[5];
    const int*   edge_types = (const int*)d_in[6];
    float* out = (float*)d_out;

    int sms = 0;
    cudaDeviceGetAttribute(&sms, cudaDevAttrMultiProcessorCount, 0);
    if (sms <= 0) sms = 148;
    cudaFuncSetAttribute(k_main, cudaFuncAttributeMaxDynamicSharedMemorySize, S_TOT * 4);

    k_prep<<<PBLK, 1024>>>(edge_types, nodes, out);
    k_main<<<sms, 512, S_TOT * 4>>>(bp_params, bp_bias, ho_params, ho_bias,
                                    edges, edge_types, out);
}